// round 2
// baseline (speedup 1.0000x reference)
#include <cuda_runtime.h>
#include <math.h>

#define H 1024
#define VOCAB 50257

#define GATE_ROWB   512          // row blocks in gates kernel (8 rows each)
#define GATE_PFB    120          // prefetch blocks appended to gates grid
#define LOGIT_NPB   3142         // ceil(50257 / 16)
#define PF_LINES    196608       // 24 MB / 128B per gates kernel

// Scratch (__device__ globals — allocation-free rule)
__device__ float g_x[H];
__device__ float g_h1[H], g_c1[H], g_h2[H], g_c2[H];
__device__ float g_gates1[4 * H], g_gates2[4 * H];
__device__ float2 g_pairs[LOGIT_NPB];
__device__ float g_lse;

// ---------------------------------------------------------------------------
__device__ __forceinline__ float sigmoidf_fast(float x) {
    return 1.f / (1.f + __expf(-x));
}

__device__ __forceinline__ void merge_pair(float& m, float& s, float m2, float s2) {
    if (m2 > m) { float t = s; s = s2 + t * __expf(m - m2); m = m2; }
    else if (m2 != -INFINITY) { s += s2 * __expf(m2 - m); }
}

// ---------------------------------------------------------------------------
// Embedding row gather: g_x = emb[input_id[0], :]
// ---------------------------------------------------------------------------
__global__ void embed_kernel(const float* __restrict__ emb,
                             const int* __restrict__ id) {
    int row = id[0];
    const float4* src = (const float4*)(emb + (long)row * H);
    float4* dst = (float4*)g_x;
    int i = threadIdx.x;
    if (i < H / 4) dst[i] = src[i];
}

// ---------------------------------------------------------------------------
// Gates GEMV: 128 threads, 4 warps, 2 rows/warp (front-batched 32x float4),
// plus GATE_PFB trailing blocks that prefetch a 24MB chunk of W_out into L2.
// ---------------------------------------------------------------------------
__global__ void __launch_bounds__(128) gates_kernel(
        const float* __restrict__ Wih, const float* __restrict__ Whh,
        const float* __restrict__ bih, const float* __restrict__ bhh,
        const float* __restrict__ xin, const float* __restrict__ hin,
        float* __restrict__ gates_out,
        const char* __restrict__ pf_base) {

    if (blockIdx.x >= GATE_ROWB) {
        // prefetch W_out chunk into L2 with evict_last priority
        int idx = (blockIdx.x - GATE_ROWB) * 128 + threadIdx.x;
        for (int i = idx; i < PF_LINES; i += GATE_PFB * 128) {
            asm volatile("prefetch.global.L2::evict_last [%0];"
                         :: "l"(pf_base + (long)i * 128));
        }
        return;
    }

    __shared__ float4 sx[H / 4];
    __shared__ float4 sh[H / 4];
    int t = threadIdx.x;
    const float4* x4 = (const float4*)xin;
    const float4* h4 = (const float4*)hin;
    for (int i = t; i < H / 4; i += 128) {
        float4 v = x4[i];
        v.x = fmaxf(v.x, 0.f); v.y = fmaxf(v.y, 0.f);
        v.z = fmaxf(v.z, 0.f); v.w = fmaxf(v.w, 0.f);
        sx[i] = v;
        sh[i] = h4[i];
    }
    __syncthreads();

    int warp = t >> 5, lane = t & 31;
    int row0 = blockIdx.x * 8 + warp * 2;   // 2 consecutive rows per warp

    const float4* wi0 = (const float4*)(Wih + (long)row0 * H);
    const float4* wh0 = (const float4*)(Whh + (long)row0 * H);
    const float4* wi1 = wi0 + H / 4;
    const float4* wh1 = wh0 + H / 4;

    float4 a0[8], b0[8], a1[8], b1[8];
#pragma unroll
    for (int k = 0; k < 8; k++) a0[k] = wi0[k * 32 + lane];
#pragma unroll
    for (int k = 0; k < 8; k++) b0[k] = wh0[k * 32 + lane];
#pragma unroll
    for (int k = 0; k < 8; k++) a1[k] = wi1[k * 32 + lane];
#pragma unroll
    for (int k = 0; k < 8; k++) b1[k] = wh1[k * 32 + lane];

    float acc0 = 0.f, acc1 = 0.f;
#pragma unroll
    for (int k = 0; k < 8; k++) {
        int idx = k * 32 + lane;
        float4 x = sx[idx];
        float4 h = sh[idx];
        acc0 += a0[k].x * x.x + a0[k].y * x.y + a0[k].z * x.z + a0[k].w * x.w;
        acc0 += b0[k].x * h.x + b0[k].y * h.y + b0[k].z * h.z + b0[k].w * h.w;
        acc1 += a1[k].x * x.x + a1[k].y * x.y + a1[k].z * x.z + a1[k].w * x.w;
        acc1 += b1[k].x * h.x + b1[k].y * h.y + b1[k].z * h.z + b1[k].w * h.w;
    }
#pragma unroll
    for (int o = 16; o > 0; o >>= 1) {
        acc0 += __shfl_down_sync(0xffffffffu, acc0, o);
        acc1 += __shfl_down_sync(0xffffffffu, acc1, o);
    }
    if (lane == 0) {
        gates_out[row0]     = acc0 + bih[row0] + bhh[row0];
        gates_out[row0 + 1] = acc1 + bih[row0 + 1] + bhh[row0 + 1];
    }
}

// ---------------------------------------------------------------------------
// LSTM elementwise (torch gate order i, f, g, o); optional output tail write.
// ---------------------------------------------------------------------------
__global__ void act_kernel(const float* __restrict__ gates,
                           const float* __restrict__ cin,
                           float* __restrict__ hout,
                           float* __restrict__ cout,
                           float* __restrict__ tail, int write_tail) {
    int j = threadIdx.x;               // blockDim = 1024
    float i_ = sigmoidf_fast(gates[j]);
    float f_ = sigmoidf_fast(gates[j + H]);
    float g_ = tanhf(gates[j + 2 * H]);
    float o_ = sigmoidf_fast(gates[j + 3 * H]);
    float cn = f_ * cin[j] + i_ * g_;
    float hn = o_ * tanhf(cn);
    hout[j] = hn;
    cout[j] = cn;
    if (write_tail) {
        tail[j]     = hn;
        tail[H + j] = cn;
    }
}

// ---------------------------------------------------------------------------
// Logits GEMV: 128 threads, 4 warps, 4 rows/warp (front-batched 32x float4).
// Writes logits AND per-block online (max, sumexp) pair — no extra pass.
// ---------------------------------------------------------------------------
__global__ void __launch_bounds__(128) logits_kernel(
        const float* __restrict__ Wout, const float* __restrict__ bout,
        float* __restrict__ out) {
    __shared__ float4 shh[H / 4];
    __shared__ float2 wpairs[4];
    int t = threadIdx.x;
    const float4* h4 = (const float4*)g_h2;
    for (int i = t; i < H / 4; i += 128) shh[i] = h4[i];
    __syncthreads();

    int warp = t >> 5, lane = t & 31;
    int row0 = blockIdx.x * 16 + warp * 4;

    float4 w[4][8];
#pragma unroll
    for (int r = 0; r < 4; r++) {
        long row = row0 + r;
        const float4* p = (const float4*)(Wout + (row < VOCAB ? row : 0) * (long)H);
#pragma unroll
        for (int k = 0; k < 8; k++) w[r][k] = p[k * 32 + lane];
    }

    float acc[4] = {0.f, 0.f, 0.f, 0.f};
#pragma unroll
    for (int k = 0; k < 8; k++) {
        float4 h = shh[k * 32 + lane];
#pragma unroll
        for (int r = 0; r < 4; r++) {
            acc[r] += w[r][k].x * h.x + w[r][k].y * h.y
                    + w[r][k].z * h.z + w[r][k].w * h.w;
        }
    }
#pragma unroll
    for (int o = 16; o > 0; o >>= 1) {
#pragma unroll
        for (int r = 0; r < 4; r++)
            acc[r] += __shfl_down_sync(0xffffffffu, acc[r], o);
    }

    if (lane == 0) {
        float m = -INFINITY, s = 0.f;
#pragma unroll
        for (int r = 0; r < 4; r++) {
            int row = row0 + r;
            if (row < VOCAB) {
                float v = acc[r] + bout[row];
                out[row] = v;
                merge_pair(m, s, v, 1.0f);
            }
        }
        wpairs[warp] = make_float2(m, s);
    }
    __syncthreads();
    if (t == 0) {
        float m = wpairs[0].x, s = wpairs[0].y;
#pragma unroll
        for (int wq = 1; wq < 4; wq++) merge_pair(m, s, wpairs[wq].x, wpairs[wq].y);
        g_pairs[blockIdx.x] = make_float2(m, s);
    }
}

// ---------------------------------------------------------------------------
// Reduce per-block (max, sumexp) pairs -> g_lse. One 1024-thread block.
// ---------------------------------------------------------------------------
__global__ void reduce_pairs_kernel() {
    __shared__ float2 red[32];
    int t = threadIdx.x, lane = t & 31, warp = t >> 5;
    float m = -INFINITY, s = 0.f;
    for (int i = t; i < LOGIT_NPB; i += 1024) {
        float2 p = g_pairs[i];
        merge_pair(m, s, p.x, p.y);
    }
#pragma unroll
    for (int o = 16; o > 0; o >>= 1) {
        float m2 = __shfl_down_sync(0xffffffffu, m, o);
        float s2 = __shfl_down_sync(0xffffffffu, s, o);
        merge_pair(m, s, m2, s2);
    }
    if (lane == 0) red[warp] = make_float2(m, s);
    __syncthreads();
    if (t < 32) {
        float2 p = red[t];
        m = p.x; s = p.y;
#pragma unroll
        for (int o = 16; o > 0; o >>= 1) {
            float m2 = __shfl_down_sync(0xffffffffu, m, o);
            float s2 = __shfl_down_sync(0xffffffffu, s, o);
            merge_pair(m, s, m2, s2);
        }
        if (t == 0) g_lse = m + logf(s);
    }
}

// ---------------------------------------------------------------------------
__global__ void subtract_kernel(float* __restrict__ out) {
    int i = blockIdx.x * blockDim.x + threadIdx.x;
    if (i < VOCAB) out[i] -= g_lse;
}

// ---------------------------------------------------------------------------
extern "C" void kernel_launch(void* const* d_in, const int* in_sizes, int n_in,
                              void* d_out, int out_size) {
    const int*   id   = (const int*)d_in[0];
    const float* h0   = (const float*)d_in[1];
    const float* c0   = (const float*)d_in[2];
    const float* emb  = (const float*)d_in[3];
    const float* Wih  = (const float*)d_in[4];
    const float* Whh  = (const float*)d_in[5];
    const float* bih  = (const float*)d_in[6];
    const float* bhh  = (const float*)d_in[7];
    const float* Wout = (const float*)d_in[8];
    const float* bout = (const float*)d_in[9];
    float* out = (float*)d_out;

    float *gx, *gh1, *gc1, *gh2, *gc2, *gg1, *gg2;
    cudaGetSymbolAddress((void**)&gx,  g_x);
    cudaGetSymbolAddress((void**)&gh1, g_h1);
    cudaGetSymbolAddress((void**)&gc1, g_c1);
    cudaGetSymbolAddress((void**)&gh2, g_h2);
    cudaGetSymbolAddress((void**)&gc2, g_c2);
    cudaGetSymbolAddress((void**)&gg1, g_gates1);
    cudaGetSymbolAddress((void**)&gg2, g_gates2);

    int write_tail = (out_size >= VOCAB + 2 * H) ? 1 : 0;

    embed_kernel<<<1, 256>>>(emb, id);

    // step 1: x = relu(emb row), h = h0, c = c0 ; prefetch W_out[0:24MB)
    gates_kernel<<<GATE_ROWB + GATE_PFB, 128>>>(
        Wih, Whh, bih, bhh, gx, h0, gg1, (const char*)Wout);
    act_kernel<<<1, 1024>>>(gg1, c0, gh1, gc1, out + VOCAB, 0);

    // step 2: x = relu(h1), h = h1, c = c1 ; prefetch W_out[24MB:48MB)
    gates_kernel<<<GATE_ROWB + GATE_PFB, 128>>>(
        Wih, Whh, bih, bhh, gh1, gh1, gg2,
        (const char*)Wout + (long)PF_LINES * 128);
    act_kernel<<<1, 1024>>>(gg2, gc1, gh2, gc2, out + VOCAB, write_tail);

    // vocab projection (+ online softmax pairs), then lse + subtract
    logits_kernel<<<LOGIT_NPB, 128>>>(Wout, bout, out);
    reduce_pairs_kernel<<<1, 1024>>>();
    subtract_kernel<<<(VOCAB + 255) / 256, 256>>>(out);
}